// round 16
// baseline (speedup 1.0000x reference)
#include <cuda_runtime.h>
#include <cuda_bf16.h>
#include <cuda_fp16.h>
#include <cuda_fp8.h>
#include <math.h>
#include <stdint.h>

#define Bz   128
#define LCz  512
#define LEz  512
#define Hz   512
#define Vz   128
#define TDEC 511
#define NBLK 128
#define NTHR 512
#define BHS  (Bz * Hz)   // 65536

// dynamic smem (float4 units):
//   Wp   [0, 4608)      : bf16 W fragment pack (72KB)
//   Ab   [4608, 13888)  : A panel, 64 x 145 f4 (148.5KB)  [phase A consumers]
//   scrA aliases Ab     : phase-B scratch (attn, all threads)
//   scrP [13888, 14528) : 2560 floats producer scratch (outproj/CE) 10KB
#define SMEM_BYTES 232448
#define ASTRIDE 145

#define NB(id) asm volatile("bar.sync %0, 256;" :: "r"(id) : "memory")

// ---------------- static device scratch -------------------------------------
__device__ __align__(16) float g_h[2][BHS];
__device__ __align__(16) __nv_bfloat16 g_hb16[2][BHS];
__device__ __align__(16) float g_c[BHS];
__device__ __align__(16) float g_vp[2][2][BHS];
__device__ __align__(16) float g_attn2[2][BHS];
__device__ __align__(16) __nv_bfloat16 g_ab16[2][BHS];
__device__ __align__(16) __nv_bfloat16 g_Cb16[(size_t)Bz * LCz * Vz];
__device__ __align__(16) __nv_bfloat16 g_Eb16[(size_t)Bz * LEz * Vz];
__device__ __align__(16) __nv_bfloat16 g_enc [(size_t)Bz * LCz * Hz];
__device__ __align__(16) unsigned char g_encc[(size_t)Bz * LCz * Hz];   // fp8
__device__ __align__(16) unsigned char g_Fc  [(size_t)Bz * LCz * Hz];   // fp8
__device__ __align__(16) __nv_bfloat16 g_vocb16[Vz * Hz];
__device__ __align__(16) __nv_bfloat16 g_oWb16[512 * 1024];
__device__ __align__(16) float g_Weff [2048 * Hz];
__device__ __align__(16) float g_Wcomp[2048 * Hz];
__device__ float g_beff[2048];
__device__ float g_u[Bz * Hz];
__device__ float g_corr[Bz * 2048];
__device__ int g_lidx[Bz * LCz];
__device__ int g_Lb[Bz];
__device__ float g_nll[Bz * TDEC];
__device__ float g_msk[Bz * TDEC];
__device__ float g_ps[NBLK], g_pc[NBLK];
// full-grid barrier (fence version, rare)
__device__ unsigned g_arr1[16 * 32];
__device__ unsigned g_arr0;
__device__ volatile unsigned g_gen;
// per-half two-level monotonic barrier
__device__ unsigned g_ga[2 * 8 * 32];
__device__ unsigned g_gm[2 * 32];
__device__ unsigned g_gg[2 * 32];

__device__ __forceinline__ float sigm(float x) { return 1.f / (1.f + expf(-x)); }

__device__ __forceinline__ uint32_t s2u(const void* p) {
    return (uint32_t)__cvta_generic_to_shared(p);
}
__device__ __forceinline__ uint32_t bpack(float lo, float hi) {
    __nv_bfloat162 v = __floats2bfloat162_rn(lo, hi);
    return *(uint32_t*)&v;
}
__device__ __forceinline__ void mma16(float acc[4],
    uint32_t a0, uint32_t a1, uint32_t a2, uint32_t a3,
    uint32_t b0, uint32_t b1)
{
    asm volatile("mma.sync.aligned.m16n8k16.row.col.f32.bf16.bf16.f32 "
        "{%0,%1,%2,%3},{%4,%5,%6,%7},{%8,%9},{%0,%1,%2,%3};"
        : "+f"(acc[0]), "+f"(acc[1]), "+f"(acc[2]), "+f"(acc[3])
        : "r"(a0), "r"(a1), "r"(a2), "r"(a3), "r"(b0), "r"(b1));
}
#define CPA16(dst, src) asm volatile("cp.async.cg.shared.global [%0], [%1], 16;" :: "r"(dst), "l"(src))

__device__ __forceinline__ unsigned char f2fp8(float x) {
    return (unsigned char)__nv_cvt_float_to_fp8(x, __NV_SATFINITE, __NV_E4M3);
}
__device__ __forceinline__ float2 fp8x2_to_f2(unsigned short p) {
    __half2_raw hr = __nv_cvt_fp8x2_to_halfraw2((__nv_fp8x2_storage_t)p, __NV_E4M3);
    return __half22float2(*(__half2*)&hr);
}

// ---------------- memory-order helpers --------------------------------------
__device__ __forceinline__ unsigned ld_cg_u32(const unsigned* p) {
    unsigned v;
    asm volatile("ld.global.cg.u32 %0, [%1];" : "=r"(v) : "l"(p) : "memory");
    return v;
}
__device__ __forceinline__ unsigned ld_acq_u32(const unsigned* p) {
    unsigned v;
    asm volatile("ld.acquire.gpu.global.u32 %0, [%1];" : "=r"(v) : "l"(p) : "memory");
    return v;
}
__device__ __forceinline__ unsigned atom_add_acqrel(unsigned* p, unsigned v) {
    unsigned old;
    asm volatile("atom.acq_rel.gpu.global.add.u32 %0, [%1], %2;" : "=r"(old) : "l"(p), "r"(v) : "memory");
    return old;
}
__device__ __forceinline__ void st_rel_u32(unsigned* p, unsigned v) {
    asm volatile("st.release.gpu.global.u32 [%0], %1;" :: "l"(p), "r"(v) : "memory");
}

__device__ __forceinline__ void gsync_all() {
    __syncthreads();
    if (threadIdx.x == 0) {
        __threadfence();
        unsigned gen = g_gen;
        unsigned grp = blockIdx.x >> 3;
        if (atomicAdd(&g_arr1[grp * 32], 1u) == 7u) {
            if (atomicAdd(&g_arr0, 1u) == 15u) {
                #pragma unroll
                for (int i = 0; i < 16; i++) g_arr1[i * 32] = 0u;
                g_arr0 = 0u;
                __threadfence();
                g_gen = gen + 1u;
            } else {
                while (g_gen == gen) __nanosleep(32);
            }
        } else {
            while (g_gen == gen) __nanosleep(32);
        }
        __threadfence();
    }
    __syncthreads();
}

__device__ __forceinline__ void gsync_g(int mh, int nb) {
    __syncthreads();
    if (threadIdx.x == 0) {
        unsigned* grp  = &g_ga[(mh * 8 + (nb >> 3)) * 32];
        unsigned* mst  = &g_gm[mh * 32];
        unsigned* genp = &g_gg[mh * 32];
        unsigned gen = ld_cg_u32(genp);
        bool released = false;
        if ((atom_add_acqrel(grp, 1u) & 7u) == 7u) {
            if ((atom_add_acqrel(mst, 1u) & 7u) == 7u) {
                st_rel_u32(genp, gen + 1u);
                released = true;
            }
        }
        if (!released) {
            while (ld_cg_u32(genp) == gen) __nanosleep(32);
            (void)ld_acq_u32(genp);
        }
    }
    __syncthreads();
}

// ---------------- W fragment pack (bf16, 3 K-segments) ----------------------
__device__ __forceinline__ float wget(int grow, int k,
    const float* W0, int ld0, int K0,
    const float* W1, int ld1, int K1,
    const float* W2, int ld2)
{
    if (k < K0) return W0[(size_t)grow * ld0 + k];
    if (k < K0 + K1) return W1[(size_t)grow * ld1 + (k - K0)];
    return W2[(size_t)grow * ld2 + (k - K0 - K1)];
}

__device__ void pack_Wb3(uint4* Wp, int nb, int KS16,
    const float* W0, int ld0, int K0,
    const float* W1, int ld1, int K1,
    const float* W2, int ld2)
{
    for (int idx = threadIdx.x; idx < 2 * KS16 * 32; idx += NTHR) {
        int wn  = idx / (KS16 * 32);
        int rem = idx - wn * (KS16 * 32);
        int s = rem >> 5, l = rem & 31;
        int gid = l >> 2, t0 = l & 3;
        uint32_t r[4];
        #pragma unroll
        for (int hh = 0; hh < 2; hh++) {
            int c = hh * 8 + gid;
            int jj = wn * 4 + (c >> 2);
            int gate = c & 3;
            int grow = gate * Hz + nb * 8 + jj;
            int k0 = s * 16 + t0 * 2;
            float w00 = wget(grow, k0,     W0, ld0, K0, W1, ld1, K1, W2, ld2);
            float w01 = wget(grow, k0 + 1, W0, ld0, K0, W1, ld1, K1, W2, ld2);
            float w10 = wget(grow, k0 + 8, W0, ld0, K0, W1, ld1, K1, W2, ld2);
            float w11 = wget(grow, k0 + 9, W0, ld0, K0, W1, ld1, K1, W2, ld2);
            r[hh * 2]     = bpack(w00, w01);
            r[hh * 2 + 1] = bpack(w10, w11);
        }
        Wp[idx] = make_uint4(r[0], r[1], r[2], r[3]);
    }
}

// ---------------- gates GEMM: bulk A publish; consumers-only compute --------
// Producers return right after the publish sync (caller gives them work).
template<bool DEC>
__device__ void gates_step(
    const uint4* __restrict__ Wp, float4* __restrict__ Ab,
    const __nv_bfloat16* __restrict__ xbase, int t,
    float* __restrict__ hout,
    const __nv_bfloat16* __restrict__ hb_in,
    const __nv_bfloat16* __restrict__ ab_in,
    __nv_bfloat16* __restrict__ hb_out,
    int mh, int nb, const float bias[2][4], const float* __restrict__ corr)
{
    const int NCH  = DEC ? 36 : 20;
    const int KS16 = DEC ? 72 : 40;
    int tid = threadIdx.x;
    int l = tid & 31, wrp = tid >> 5;
    bool prod = (wrp >= 8);
    int wm = wrp & 3, wn = (wrp >> 2) & 1;
    int gid = l >> 2, t0 = l & 3;
    int m16 = mh * 64 + wm * 16;
    int arow = wm * 16 + ((l >> 3) & 1) * 8 + (l & 7);
    int halfsel = l >> 4;

    uint32_t abase = s2u(Ab);

    if (prod) {
        int tid2 = tid - 256;
        int row = tid2 >> 2, cl = tid2 & 3;
        int rowb = mh * 64 + row;
        const __nv_bfloat16* s0 = xbase + (size_t)rowb * ((DEC ? LEz : LCz) * Vz) + (size_t)t * Vz;
        const __nv_bfloat16* s1 = hb_in + rowb * Hz;
        const __nv_bfloat16* s2 = DEC ? (ab_in + rowb * Hz) : s1;
        uint32_t dbase = abase + (uint32_t)(row * ASTRIDE) * 16;
        #pragma unroll
        for (int cc = 0; cc < NCH; cc++) {
            int kf4 = cc * 4 + cl;
            int k = kf4 * 8;
            const __nv_bfloat16* src =
                (k < 128) ? (s0 + k)
                : ((!DEC || k < 640) ? (s1 + (k - 128)) : (s2 + (k - 640)));
            CPA16(dbase + (uint32_t)(kf4 * 16), src);
        }
        asm volatile("cp.async.commit_group;");
        asm volatile("cp.async.wait_group 0;");
    }
    __syncthreads();   // single publish point

    if (!prod) {
        float acc[2][4];
        #pragma unroll
        for (int i = 0; i < 2; i++)
            #pragma unroll
            for (int k = 0; k < 4; k++) acc[i][k] = 0.f;

        uint32_t lbase = abase + (uint32_t)(arow * ASTRIDE + halfsel) * 16;
        const uint4* wpp = Wp + (size_t)wn * KS16 * 32 + l;
        #pragma unroll 4
        for (int cc = 0; cc < NCH; cc++) {
            #pragma unroll
            for (int kk = 0; kk < 2; kk++) {
                uint32_t addr = lbase + (uint32_t)((cc * 4 + kk * 2) * 16);
                uint32_t a0, a1, a2, a3;
                asm volatile("ldmatrix.sync.aligned.m8n8.x4.shared.b16 {%0,%1,%2,%3}, [%4];"
                             : "=r"(a0), "=r"(a1), "=r"(a2), "=r"(a3) : "r"(addr));
                uint4 wv = wpp[(size_t)(cc * 2 + kk) * 32];
                mma16(acc[0], a0, a1, a2, a3, wv.x, wv.y);
                mma16(acc[1], a0, a1, a2, a3, wv.z, wv.w);
            }
        }

        bool evn = ((t0 & 1) == 0);
        #pragma unroll
        for (int hh = 0; hh < 2; hh++) {
            float d0 = acc[hh][0], d1 = acc[hh][1], d2 = acc[hh][2], d3 = acc[hh][3];
            float x0 = __shfl_xor_sync(0xffffffffu, d0, 1);
            float x1 = __shfl_xor_sync(0xffffffffu, d1, 1);
            float x2 = __shfl_xor_sync(0xffffffffu, d2, 1);
            float x3 = __shfl_xor_sync(0xffffffffu, d3, 1);
            int j = nb * 8 + wn * 4 + hh * 2 + (t0 >> 1);
            int b = m16 + gid + (evn ? 0 : 8);
            float gi = (evn ? d0 : x2) + bias[hh][0];
            float gf = (evn ? d1 : x3) + bias[hh][1];
            float gg = (evn ? x0 : d2) + bias[hh][2];
            float go = (evn ? x1 : d3) + bias[hh][3];
            if (corr) {
                gi -= corr[b * 2048 + j];
                gf -= corr[b * 2048 + 512 + j];
                gg -= corr[b * 2048 + 1024 + j];
                go -= corr[b * 2048 + 1536 + j];
            }
            float c  = g_c[b * Hz + j];
            float cn = sigm(gf) * c + sigm(gi) * tanhf(gg);
            float hn = sigm(go) * tanhf(cn);
            g_c[b * Hz + j] = cn;
            hout[b * Hz + j] = hn;
            hb_out[b * Hz + j] = __float2bfloat16(hn);
            if (!DEC)
                g_enc[((size_t)b * LCz + t) * Hz + j] = __float2bfloat16(hn);
        }
    }
}

__device__ __forceinline__ void load_bias2(float bias[2][4],
    const float* __restrict__ bih, const float* __restrict__ bhh,
    const float* __restrict__ beff, int nb)
{
    int l = threadIdx.x & 31;
    int wn = ((threadIdx.x >> 5) >> 2) & 1;
    int t0 = l & 3;
    #pragma unroll
    for (int hh = 0; hh < 2; hh++) {
        int j = nb * 8 + wn * 4 + hh * 2 + (t0 >> 1);
        #pragma unroll
        for (int g4 = 0; g4 < 4; g4++)
            bias[hh][g4] = beff ? beff[g4 * Hz + j] : (bih[g4 * Hz + j] + bhh[g4 * Hz + j]);
    }
}

// ---------------- pad compaction (512 threads) ------------------------------
__device__ void comp_scan(int b, const int* __restrict__ C_pad, float* smf)
{
    int* sm = (int*)smf;
    int tid = threadIdx.x, lane = tid & 31, w = tid >> 5;
    int f = (C_pad[b * LCz + tid] == 0) ? 1 : 0;
    int x = f;
    #pragma unroll
    for (int o = 1; o < 32; o <<= 1) {
        int y = __shfl_up_sync(0xffffffffu, x, o);
        if (lane >= o) x += y;
    }
    if (lane == 31) sm[w] = x;
    __syncthreads();
    if (tid == 0) {
        int run = 0;
        for (int i = 0; i < 16; i++) { int v = sm[i]; sm[16 + i] = run; run += v; }
        sm[32] = run;
    }
    __syncthreads();
    int excl = sm[16 + w] + x - f;
    if (f) g_lidx[b * LCz + excl] = tid;
    if (tid == 0) g_Lb[b] = sm[32];
    __syncthreads();
}

__device__ void build_F(int b, const float* __restrict__ att_W, float* se)
{
    int tid = threadIdx.x;
    int Lb = g_Lb[b];
    for (int ci0 = 0; ci0 < Lb; ci0 += 32) {
        int R = min(32, Lb - ci0);
        for (int idx = tid; idx < R * 512; idx += NTHR) {
            int r = idx >> 9, j = idx & 511;
            int l = g_lidx[b * LCz + ci0 + r];
            __nv_bfloat16 hv = g_enc[((size_t)b * LCz + l) * Hz + j];
            float fv = __bfloat162float(hv);
            se[j * 36 + r] = fv;
            g_encc[((size_t)b * LCz + ci0 + r) * Hz + j] = f2fp8(fv);
        }
        __syncthreads();
        {
            int k = tid;
            float acc[32];
            #pragma unroll
            for (int i = 0; i < 32; i++) acc[i] = 0.f;
            for (int j = 0; j < 512; j++) {
                float wv = att_W[j * Hz + k];
                #pragma unroll
                for (int g4 = 0; g4 < 8; g4++) {
                    float4 e = *(const float4*)&se[j * 36 + g4 * 4];
                    acc[g4 * 4 + 0] += e.x * wv;
                    acc[g4 * 4 + 1] += e.y * wv;
                    acc[g4 * 4 + 2] += e.z * wv;
                    acc[g4 * 4 + 3] += e.w * wv;
                }
            }
            for (int r = 0; r < R; r++)
                g_Fc[((size_t)b * LCz + ci0 + r) * Hz + k] = f2fp8(acc[r]);
        }
        __syncthreads();
    }
}

__device__ void calc_u(int b, const float* __restrict__ out_W,
                       const float* __restrict__ out_b, float* scr)
{
    int tid = threadIdx.x;
    __syncthreads();
    if (tid < Hz) scr[tid] = g_h[0][b * Hz + tid];
    __syncthreads();
    if (tid < Hz) {
        const float* wr = out_W + (size_t)tid * (2 * Hz);
        float acc = 0.f;
        for (int h = 0; h < Hz; h += 4) {
            float4 w4 = *(const float4*)(wr + h);
            acc += w4.x * scr[h] + w4.y * scr[h + 1] + w4.z * scr[h + 2] + w4.w * scr[h + 3];
        }
        g_u[b * Hz + tid] = acc + out_b[tid];
    }
    __syncthreads();
}

__device__ void compose(const float* __restrict__ dec_Wih, const float* __restrict__ dec_Whh,
                        const float* __restrict__ dec_bih, const float* __restrict__ dec_bhh,
                        const float* __restrict__ out_W, const float* __restrict__ out_b)
{
    int bid = blockIdx.x, tid = threadIdx.x;
    if (tid >= 256) return;
    int g = bid * 16 + (tid >> 4);
    int c0 = (tid & 15) * 32;
    const float* wv = dec_Wih + (size_t)g * (Vz + Hz) + Vz;
    #pragma unroll 1
    for (int pass = 0; pass < 2; pass++) {
        float acc[32];
        #pragma unroll
        for (int i = 0; i < 32; i++) acc[i] = 0.f;
        float accb = 0.f;
        for (int v = 0; v < Hz; v++) {
            float w = wv[v];
            const float* owr = out_W + (size_t)v * (2 * Hz) + pass * Hz + c0;
            #pragma unroll
            for (int i = 0; i < 32; i += 4) {
                float4 o = *(const float4*)(owr + i);
                acc[i] += w * o.x; acc[i + 1] += w * o.y;
                acc[i + 2] += w * o.z; acc[i + 3] += w * o.w;
            }
            if (pass == 0) accb += w * out_b[v];
        }
        if (pass == 0) {
            for (int i = 0; i < 32; i++)
                g_Weff[(size_t)g * Hz + c0 + i] = dec_Whh[(size_t)g * Hz + c0 + i] + acc[i];
            if ((tid & 15) == 0) g_beff[g] = dec_bih[g] + dec_bhh[g] + accb;
        } else {
            for (int i = 0; i < 32; i++)
                g_Wcomp[(size_t)g * Hz + c0 + i] = acc[i];
        }
    }
}

__device__ void calc_c(int b, const float* __restrict__ dec_Wih, float* scr)
{
    int tid = threadIdx.x;
    __syncthreads();
    if (tid < Hz) scr[tid] = g_u[b * Hz + tid];
    __syncthreads();
    for (int g = tid; g < 2048; g += NTHR) {
        const float* wv = dec_Wih + (size_t)g * (Vz + Hz) + Vz;
        float acc = 0.f;
        for (int v = 0; v < Hz; v += 4) {
            float4 w4 = *(const float4*)(wv + v);
            acc += w4.x * scr[v] + w4.y * scr[v + 1] + w4.z * scr[v + 2] + w4.w * scr[v + 3];
        }
        g_corr[b * 2048 + g] = acc;
    }
}

// ---------------- attention: ALL 512 threads, fp8 streams --------------------
__device__ void attn_block512(int b, const float* __restrict__ hcur,
                              float* __restrict__ dst, __nv_bfloat16* __restrict__ dstb,
                              float* sm)
{
    float* ss   = sm;          // 512
    float* red  = sm + 512;    // 16
    float* sca  = sm + 528;    // 2
    float* wacc = sm + 544;    // 16 * 512
    int tid = threadIdx.x, lane = tid & 31, w = tid >> 5;  // w < 16
    int Lb = g_Lb[b];

    float qreg[16];
    const float* hb = hcur + b * Hz + lane * 16;
    #pragma unroll
    for (int i = 0; i < 16; i += 4) {
        float4 v = *(const float4*)(hb + i);
        qreg[i] = v.x; qreg[i + 1] = v.y; qreg[i + 2] = v.z; qreg[i + 3] = v.w;
    }

    const unsigned char* Fb = g_Fc + (size_t)b * LCz * Hz;
    #pragma unroll 4
    for (int l = w; l < Lb; l += 16) {
        uint4 u0 = *(const uint4*)(Fb + (size_t)l * Hz + lane * 16);
        const unsigned short* p2 = (const unsigned short*)&u0;
        float acc = 0.f;
        #pragma unroll
        for (int i = 0; i < 8; i++) {
            float2 f = fp8x2_to_f2(p2[i]);
            acc += f.x * qreg[2 * i] + f.y * qreg[2 * i + 1];
        }
        #pragma unroll
        for (int o = 16; o > 0; o >>= 1) acc += __shfl_xor_sync(0xffffffffu, acc, o);
        if (lane == 0) ss[l] = acc;
    }
    __syncthreads();

    float m = -INFINITY;
    for (int l = tid; l < Lb; l += NTHR) m = fmaxf(m, ss[l]);
    #pragma unroll
    for (int o = 16; o > 0; o >>= 1) m = fmaxf(m, __shfl_xor_sync(0xffffffffu, m, o));
    if (lane == 0) red[w] = m;
    __syncthreads();
    if (tid == 0) {
        float mm = red[0];
        for (int i = 1; i < 16; i++) mm = fmaxf(mm, red[i]);
        sca[0] = mm;
    }
    __syncthreads();
    float bmax = sca[0];

    float s = 0.f;
    for (int l = tid; l < Lb; l += NTHR) {
        float e = expf(ss[l] - bmax);
        ss[l] = e;
        s += e;
    }
    #pragma unroll
    for (int o = 16; o > 0; o >>= 1) s += __shfl_xor_sync(0xffffffffu, s, o);
    if (lane == 0) red[w] = s;
    __syncthreads();
    if (tid == 0) {
        float t2 = 0.f;
        for (int i = 0; i < 16; i++) t2 += red[i];
        sca[1] = t2;
    }
    __syncthreads();
    float inv = 1.f / sca[1];

    float acc2[16];
    #pragma unroll
    for (int i = 0; i < 16; i++) acc2[i] = 0.f;
    const unsigned char* Eb = g_encc + (size_t)b * LCz * Hz;
    #pragma unroll 4
    for (int l = w; l < Lb; l += 16) {
        float d = ss[l];
        uint4 u0 = *(const uint4*)(Eb + (size_t)l * Hz + lane * 16);
        const unsigned short* p2 = (const unsigned short*)&u0;
        #pragma unroll
        for (int i = 0; i < 8; i++) {
            float2 f = fp8x2_to_f2(p2[i]);
            acc2[2 * i]     += d * f.x;
            acc2[2 * i + 1] += d * f.y;
        }
    }
    #pragma unroll
    for (int i = 0; i < 16; i++) wacc[w * Hz + lane * 16 + i] = acc2[i];
    __syncthreads();

    {
        int h = tid;   // NTHR == Hz
        float t2 = 0.f;
        #pragma unroll
        for (int ww = 0; ww < 16; ww++) t2 += wacc[ww * Hz + h];
        float v = t2 * inv;
        dst[b * Hz + h] = v;
        dstb[b * Hz + h] = __float2bfloat16(v);
    }
    __syncthreads();
}

// ---------------- out-proj (producer warps, single-buffer scrP) --------------
__device__ void outproj16(const float* __restrict__ h_src,
                          const float* __restrict__ attn_src,
                          const float* __restrict__ out_b,
                          float* __restrict__ vout, float* sm, int mh, int t256)
{
    NB(2);
    int bid = blockIdx.x;
    int gb = bid >> 1;
    int m0 = mh * 64 + (gb & 3) * 16;
    int n0 = ((gb >> 2) & 7) * 64;
    int split = (gb >> 5) & 1;
    const float* Asrc = (split == 0) ? h_src : attn_src;

    int arow = t256 & 15, akg = t256 >> 4;
    int wr = t256 >> 2, wkg = t256 & 3;
    int m = t256 >> 4, ng = t256 & 15;

    const float* ap = Asrc + (size_t)(m0 + arow) * Hz + akg * 8;
    const __nv_bfloat16* wp = g_oWb16 + (size_t)(n0 + wr) * 1024 + split * Hz + wkg * 8;

    float* As = sm;          // 512
    float* Ws = sm + 512;    // 2048

    float4 pa0, pa1;
    uint4 pw;
    if (t256 < 64) { pa0 = *(const float4*)ap; pa1 = *(const float4*)(ap + 4); }
    pw = *(const uint4*)wp;

    float acc[4] = {0.f, 0.f, 0.f, 0.f};
    for (int it = 0; it < 16; it++) {
        if (t256 < 64) {
            int kb = akg * 8;
            As[(kb + 0) * 16 + arow] = pa0.x; As[(kb + 1) * 16 + arow] = pa0.y;
            As[(kb + 2) * 16 + arow] = pa0.z; As[(kb + 3) * 16 + arow] = pa0.w;
            As[(kb + 4) * 16 + arow] = pa1.x; As[(kb + 5) * 16 + arow] = pa1.y;
            As[(kb + 6) * 16 + arow] = pa1.z; As[(kb + 7) * 16 + arow] = pa1.w;
        }
        {
            int kb = wkg * 8;
            const __nv_bfloat162* ph = (const __nv_bfloat162*)&pw;
            #pragma unroll
            for (int i = 0; i < 4; i++) {
                float2 f = __bfloat1622float2(ph[i]);
                Ws[(kb + 2 * i) * 64 + wr]     = f.x;
                Ws[(kb + 2 * i + 1) * 64 + wr] = f.y;
            }
        }
        NB(2);
        if (it < 15) {
            if (t256 < 64) {
                const float* ap2 = ap + (it + 1) * 32;
                pa0 = *(const float4*)ap2; pa1 = *(const float4*)(ap2 + 4);
            }
            pw = *(const uint4*)(wp + (it + 1) * 32);
        }
        #pragma unroll
        for (int kk = 0; kk < 32; kk++) {
            float a = As[kk * 16 + m];
            float4 w4 = *(const float4*)&Ws[kk * 64 + ng * 4];
            acc[0] += a * w4.x; acc[1] += a * w4.y;
            acc[2] += a * w4.z; acc[3] += a * w4.w;
        }
        NB(2);   // guard smem reuse by next store
    }
    #pragma unroll
    for (int i = 0; i < 4; i++) {
        int n = n0 + ng * 4 + i;
        float v = acc[i] + ((split == 0) ? out_b[n] : 0.f);
        vout[(size_t)split * BHS + (m0 + m) * Hz + n] = v;
    }
}

// ---------------- logits + CE (256 threads, given barrier id) ----------------
__device__ void logits_ce(int b, int tt, const int* __restrict__ E,
                          const float* __restrict__ vp,
                          const float* __restrict__ voc_b, float* sm,
                          int t256, int barid)
{
    float* st = sm;
    float* sl = sm + 512;
    int lane = t256 & 31, w = t256 >> 5;
    NB(barid);

    for (int i = t256; i < Hz; i += 256)
        st[i] = tanhf(vp[b * Hz + i] + vp[BHS + b * Hz + i]);
    NB(barid);

    float sreg[16];
    #pragma unroll
    for (int i = 0; i < 16; i++) sreg[i] = st[lane * 16 + i];

    for (int v = w; v < Vz; v += 8) {
        const __nv_bfloat16* wr = g_vocb16 + (size_t)v * Hz + lane * 16;
        uint4 u0 = *(const uint4*)wr;
        uint4 u1 = *(const uint4*)(wr + 8);
        const __nv_bfloat162* h0 = (const __nv_bfloat162*)&u0;
        const __nv_bfloat162* h1 = (const __nv_bfloat162*)&u1;
        float acc = 0.f;
        #pragma unroll
        for (int i = 0; i < 4; i++) {
            float2 f0 = __bfloat1622float2(h0[i]);
            float2 f1 = __bfloat1622float2(h1[i]);
            acc += f0.x * sreg[2 * i]     + f0.y * sreg[2 * i + 1];
            acc += f1.x * sreg[8 + 2 * i] + f1.y * sreg[8 + 2 * i + 1];
        }
        #pragma unroll
        for (int o = 16; o > 0; o >>= 1) acc += __shfl_xor_sync(0xffffffffu, acc, o);
        if (lane == 0) sl[v] = acc + voc_b[v];
    }
    NB(barid);

    if (w == 0) {
        float m = -INFINITY;
        for (int v = lane; v < Vz; v += 32) m = fmaxf(m, sl[v]);
        #pragma unroll
        for (int o = 16; o > 0; o >>= 1) m = fmaxf(m, __shfl_xor_sync(0xffffffffu, m, o));
        float s = 0.f;
        for (int v = lane; v < Vz; v += 32) s += expf(sl[v] - m);
        #pragma unroll
        for (int o = 16; o > 0; o >>= 1) s += __shfl_xor_sync(0xffffffffu, s, o);
        if (lane == 0) {
            int tv = E[b * LEz + tt + 1];
            int idx = b * TDEC + tt;
            if (tv != 0) { g_nll[idx] = m + logf(s) - sl[tv]; g_msk[idx] = 1.f; }
            else         { g_nll[idx] = 0.f;                  g_msk[idx] = 0.f; }
        }
    }
    NB(barid);
}

// ---------------- the single persistent kernel ------------------------------
__global__ void __launch_bounds__(NTHR, 1) persist_kernel(
    const float* __restrict__ C,       const int* __restrict__ C_pad,
    const int* __restrict__ E,         const float* __restrict__ E_emb,
    const float* __restrict__ enc_Wih, const float* __restrict__ enc_Whh,
    const float* __restrict__ enc_bih, const float* __restrict__ enc_bhh,
    const float* __restrict__ dec_Wih, const float* __restrict__ dec_Whh,
    const float* __restrict__ dec_bih, const float* __restrict__ dec_bhh,
    const float* __restrict__ att_W,   const float* __restrict__ out_W,
    const float* __restrict__ out_b,   const float* __restrict__ voc_W,
    const float* __restrict__ voc_b,   float* __restrict__ out)
{
    extern __shared__ __align__(16) float4 dsm[];
    uint4*  Wp   = (uint4*)dsm;
    float4* Ab   = dsm + 4608;
    float*  scrA = (float*)(dsm + 4608);     // aliases Ab (phase-B / pre-dec)
    float*  scrP = (float*)(dsm + 13888);    // producer scratch, non-aliased

    int bid = blockIdx.x, tid = threadIdx.x;
    int lane = tid & 31, w = tid >> 5;
    int mh = bid & 1, nb = bid >> 1;
    int mhb = mh * 64 + nb;

    // ---- init + bf16 pre-conversions ----
    for (int i = bid * NTHR + tid; i < BHS; i += NBLK * NTHR) {
        g_h[0][i] = 0.f; g_c[i] = 0.f;
        g_hb16[0][i] = __float2bfloat16(0.f);
        g_ab16[0][i] = __float2bfloat16(0.f);
        g_ab16[1][i] = __float2bfloat16(0.f);
    }
    float* vpf = (float*)g_vp;
    for (int i = bid * NTHR + tid; i < 4 * BHS; i += NBLK * NTHR) vpf[i] = 0.f;
    float* apf = (float*)g_attn2;
    for (int i = bid * NTHR + tid; i < 2 * BHS; i += NBLK * NTHR) apf[i] = 0.f;
    for (int i = bid * NTHR + tid; i < Vz * Hz; i += NBLK * NTHR)
        g_vocb16[i] = __float2bfloat16(voc_W[i]);
    for (size_t i = bid * NTHR + tid; i < (size_t)Bz * LCz * Vz; i += NBLK * NTHR)
        g_Cb16[i] = __float2bfloat16(C[i]);
    for (size_t i = bid * NTHR + tid; i < (size_t)Bz * LEz * Vz; i += NBLK * NTHR)
        g_Eb16[i] = __float2bfloat16(E_emb[i]);
    for (int i = bid * NTHR + tid; i < 512 * 1024; i += NBLK * NTHR)
        g_oWb16[i] = __float2bfloat16(out_W[i]);
    gsync_all();

    // ---- encoder ----
    pack_Wb3(Wp, nb, 40, enc_Wih, Vz, Vz, enc_Whh, Hz, Hz, enc_Whh, Hz);
    __syncthreads();
    float biasE[2][4];
    load_bias2(biasE, enc_bih, enc_bhh, nullptr, nb);
    for (int t = 0; t < LCz; t++) {
        gates_step<false>(Wp, Ab, g_Cb16, t, g_h[1 - (t & 1)],
                          g_hb16[t & 1], nullptr, g_hb16[1 - (t & 1)],
                          mh, nb, biasE, nullptr);
        gsync_g(mh, nb);
    }

    // ---- pre-decoder (own batch) ----
    comp_scan(mhb, C_pad, scrA);
    build_F(mhb, att_W, (float*)dsm);
    calc_u(mhb, out_W, out_b, scrA);
    calc_c(mhb, dec_Wih, scrA);

    // ---- composition (shared) => full barrier ----
    compose(dec_Wih, dec_Whh, dec_bih, dec_bhh, out_W, out_b);
    gsync_all();

    // ---- decoder ----
    pack_Wb3(Wp, nb, 72, dec_Wih, Vz + Hz, Vz, g_Weff, Hz, Hz, g_Wcomp, Hz);
    __syncthreads();
    float biasD[2][4];
    load_bias2(biasD, dec_bih, dec_bhh, g_beff, nb);

    for (int t = 0; t < TDEC; t++) {
        // Phase A: consumers gates(t) || producers outproj(t-1) + CE(t-2)
        gates_step<true>(Wp, Ab, g_Eb16, t, g_h[1 - (t & 1)],
                         g_hb16[t & 1], g_ab16[(t + 1) & 1], g_hb16[1 - (t & 1)],
                         mh, nb, biasD, (t == 0) ? g_corr : nullptr);
        if (tid >= 256) {
            int t256 = tid - 256;
            if (t >= 1)
                outproj16(g_h[t & 1], g_attn2[(t + 1) & 1], out_b,
                          (float*)g_vp[(t + 1) & 1], scrP, mh, t256);
            if (t >= 2)
                logits_ce(mhb, t - 2, E, (const float*)g_vp[t & 1], voc_b, scrP,
                          t256, 2);
        }
        gsync_g(mh, nb);

        // Phase B: attention(t) on all 512 threads
        attn_block512(mhb, g_h[1 - (t & 1)], g_attn2[t & 1], g_ab16[t & 1], scrA);
        gsync_g(mh, nb);
    }

    // ---- tail: outproj(510) (group B) || CE(509) (group A); then CE(510) ----
    if (tid < 256) {
        logits_ce(mhb, TDEC - 2, E, (const float*)g_vp[1], voc_b, scrA, tid, 1);
    } else {
        outproj16(g_h[1], g_attn2[0], out_b, (float*)g_vp[0], scrP, mh, tid - 256);
    }
    gsync_g(mh, nb);
    if (tid < 256)
        logits_ce(mhb, TDEC - 1, E, (const float*)g_vp[0], voc_b, scrA, tid, 1);
    __syncthreads();

    // ---- per-batch reduction ----
    {
        float s = 0.f, c = 0.f;
        for (int i = tid; i < TDEC; i += NTHR) {
            s += g_nll[mhb * TDEC + i];
            c += g_msk[mhb * TDEC + i];
        }
        #pragma unroll
        for (int o = 16; o > 0; o >>= 1) {
            s += __shfl_xor_sync(0xffffffffu, s, o);
            c += __shfl_xor_sync(0xffffffffu, c, o);
        }
        __syncthreads();
        if (lane == 0) { scrA[w] = s; scrA[16 + w] = c; }
        __syncthreads();
        if (tid == 0) {
            float ts = 0.f, tc = 0.f;
            for (int i = 0; i < 16; i++) { ts += scrA[i]; tc += scrA[16 + i]; }
            g_ps[bid] = ts; g_pc[bid] = tc;
        }
    }
    gsync_all();
    if (bid == 0 && tid == 0) {
        float ts = 0.f, tc = 0.f;
        for (int i = 0; i < NBLK; i++) { ts += g_ps[i]; tc += g_pc[i]; }
        out[0] = ts / fmaxf(tc, 1.f);
    }
}

// ---------------- host entry ------------------------------------------------
extern "C" void kernel_launch(void* const* d_in, const int* in_sizes, int n_in,
                              void* d_out, int out_size)
{
    cudaFuncSetAttribute((const void*)persist_kernel,
                         cudaFuncAttributeMaxDynamicSharedMemorySize, SMEM_BYTES);
    persist_kernel<<<NBLK, NTHR, SMEM_BYTES>>>(
        (const float*)d_in[0],  (const int*)d_in[1],
        (const int*)d_in[2],    (const float*)d_in[3],
        (const float*)d_in[4],  (const float*)d_in[5],
        (const float*)d_in[6],  (const float*)d_in[7],
        (const float*)d_in[8],  (const float*)d_in[9],
        (const float*)d_in[10], (const float*)d_in[11],
        (const float*)d_in[12], (const float*)d_in[13],
        (const float*)d_in[14], (const float*)d_in[15],
        (const float*)d_in[16], (float*)d_out);
}

// round 17
// speedup vs baseline: 1.1346x; 1.1346x over previous
#include <cuda_runtime.h>
#include <cuda_bf16.h>
#include <cuda_fp16.h>
#include <cuda_fp8.h>
#include <math.h>
#include <stdint.h>

#define Bz   128
#define LCz  512
#define LEz  512
#define Hz   512
#define Vz   128
#define TDEC 511
#define NBLK 128
#define NTHR 512
#define BHS  (Bz * Hz)   // 65536

#define DSTR   1160      // dec panel row stride (bf16): x128|h512|attn512|pad8
#define ESTR   648       // enc panel row stride: x128|h512|pad8
#define DSTRF4 145
#define ESTRF4 81

// dynamic smem (f4): Wp[0,4608) 72KB | Ab[4608,13888) 148.5KB | mbar@13888 | scrR[13889,14401) 8KB
//   scrA aliases Ab (phase-B scratch), scrB = scrA + 4624 floats
#define SMEM_BYTES 230416

#define NB(id) asm volatile("bar.sync %0, 256;" :: "r"(id) : "memory")

// ---------------- static device scratch -------------------------------------
__device__ __align__(16) float g_h[2][BHS];
__device__ __align__(16) float g_c[BHS];
__device__ __align__(16) float g_vp[2][2][BHS];
__device__ __align__(16) float g_attn2[2][BHS];
__device__ __align__(16) __nv_bfloat16 g_ApD[(size_t)512 * 128 * DSTR];  // 152MB
__device__ __align__(16) __nv_bfloat16 g_ApE[(size_t)512 * 128 * ESTR];  // 85MB
__device__ __align__(16) __nv_bfloat16 g_enc [(size_t)Bz * LCz * Hz];
__device__ __align__(16) unsigned char g_encc[(size_t)Bz * LCz * Hz];    // fp8
__device__ __align__(16) unsigned char g_Fc  [(size_t)Bz * LCz * Hz];    // fp8
__device__ __align__(16) __nv_bfloat16 g_vocb16[Vz * Hz];
__device__ __align__(16) __nv_bfloat16 g_oWb16[512 * 1024];
__device__ __align__(16) float g_Weff [2048 * Hz];
__device__ __align__(16) float g_Wcomp[2048 * Hz];
__device__ float g_beff[2048];
__device__ float g_u[Bz * Hz];
__device__ float g_corr[Bz * 2048];
__device__ int g_lidx[Bz * LCz];
__device__ int g_Lb[Bz];
__device__ float g_nll[Bz * TDEC];
__device__ float g_msk[Bz * TDEC];
__device__ float g_ps[NBLK], g_pc[NBLK];
// full-grid barrier (fence version, rare)
__device__ unsigned g_arr1[16 * 32];
__device__ unsigned g_arr0;
__device__ volatile unsigned g_gen;
// per-half two-level monotonic barrier
__device__ unsigned g_ga[2 * 8 * 32];
__device__ unsigned g_gm[2 * 32];
__device__ unsigned g_gg[2 * 32];

__device__ __forceinline__ float sigm(float x) { return 1.f / (1.f + expf(-x)); }

__device__ __forceinline__ uint32_t s2u(const void* p) {
    return (uint32_t)__cvta_generic_to_shared(p);
}
__device__ __forceinline__ uint32_t bpack(float lo, float hi) {
    __nv_bfloat162 v = __floats2bfloat162_rn(lo, hi);
    return *(uint32_t*)&v;
}
__device__ __forceinline__ void mma16(float acc[4],
    uint32_t a0, uint32_t a1, uint32_t a2, uint32_t a3,
    uint32_t b0, uint32_t b1)
{
    asm volatile("mma.sync.aligned.m16n8k16.row.col.f32.bf16.bf16.f32 "
        "{%0,%1,%2,%3},{%4,%5,%6,%7},{%8,%9},{%0,%1,%2,%3};"
        : "+f"(acc[0]), "+f"(acc[1]), "+f"(acc[2]), "+f"(acc[3])
        : "r"(a0), "r"(a1), "r"(a2), "r"(a3), "r"(b0), "r"(b1));
}

__device__ __forceinline__ unsigned char f2fp8(float x) {
    return (unsigned char)__nv_cvt_float_to_fp8(x, __NV_SATFINITE, __NV_E4M3);
}
__device__ __forceinline__ float2 fp8x2_to_f2(unsigned short p) {
    __half2_raw hr = __nv_cvt_fp8x2_to_halfraw2((__nv_fp8x2_storage_t)p, __NV_E4M3);
    return __half22float2(*(__half2*)&hr);
}

// ---------------- memory-order helpers --------------------------------------
__device__ __forceinline__ unsigned ld_cg_u32(const unsigned* p) {
    unsigned v;
    asm volatile("ld.global.cg.u32 %0, [%1];" : "=r"(v) : "l"(p) : "memory");
    return v;
}
__device__ __forceinline__ unsigned ld_acq_u32(const unsigned* p) {
    unsigned v;
    asm volatile("ld.acquire.gpu.global.u32 %0, [%1];" : "=r"(v) : "l"(p) : "memory");
    return v;
}
__device__ __forceinline__ unsigned atom_add_acqrel(unsigned* p, unsigned v) {
    unsigned old;
    asm volatile("atom.acq_rel.gpu.global.add.u32 %0, [%1], %2;" : "=r"(old) : "l"(p), "r"(v) : "memory");
    return old;
}
__device__ __forceinline__ void st_rel_u32(unsigned* p, unsigned v) {
    asm volatile("st.release.gpu.global.u32 [%0], %1;" :: "l"(p), "r"(v) : "memory");
}

__device__ __forceinline__ void gsync_all() {
    __syncthreads();
    if (threadIdx.x == 0) {
        __threadfence();
        unsigned gen = g_gen;
        unsigned grp = blockIdx.x >> 3;
        if (atomicAdd(&g_arr1[grp * 32], 1u) == 7u) {
            if (atomicAdd(&g_arr0, 1u) == 15u) {
                #pragma unroll
                for (int i = 0; i < 16; i++) g_arr1[i * 32] = 0u;
                g_arr0 = 0u;
                __threadfence();
                g_gen = gen + 1u;
            } else {
                while (g_gen == gen) __nanosleep(32);
            }
        } else {
            while (g_gen == gen) __nanosleep(32);
        }
        __threadfence();
    }
    __syncthreads();
}

__device__ __forceinline__ void gsync_g(int mh, int nb) {
    __syncthreads();
    if (threadIdx.x == 0) {
        unsigned* grp  = &g_ga[(mh * 8 + (nb >> 3)) * 32];
        unsigned* mst  = &g_gm[mh * 32];
        unsigned* genp = &g_gg[mh * 32];
        unsigned gen = ld_cg_u32(genp);
        bool released = false;
        if ((atom_add_acqrel(grp, 1u) & 7u) == 7u) {
            if ((atom_add_acqrel(mst, 1u) & 7u) == 7u) {
                st_rel_u32(genp, gen + 1u);
                released = true;
            }
        }
        if (!released) {
            while (ld_cg_u32(genp) == gen) __nanosleep(32);
            (void)ld_acq_u32(genp);
        }
    }
    __syncthreads();
}

// ---------------- W fragment pack (bf16, 3 K-segments) ----------------------
__device__ __forceinline__ float wget(int grow, int k,
    const float* W0, int ld0, int K0,
    const float* W1, int ld1, int K1,
    const float* W2, int ld2)
{
    if (k < K0) return W0[(size_t)grow * ld0 + k];
    if (k < K0 + K1) return W1[(size_t)grow * ld1 + (k - K0)];
    return W2[(size_t)grow * ld2 + (k - K0 - K1)];
}

__device__ void pack_Wb3(uint4* Wp, int nb, int KS16,
    const float* W0, int ld0, int K0,
    const float* W1, int ld1, int K1,
    const float* W2, int ld2)
{
    for (int idx = threadIdx.x; idx < 2 * KS16 * 32; idx += NTHR) {
        int wn  = idx / (KS16 * 32);
        int rem = idx - wn * (KS16 * 32);
        int s = rem >> 5, l = rem & 31;
        int gid = l >> 2, t0 = l & 3;
        uint32_t r[4];
        #pragma unroll
        for (int hh = 0; hh < 2; hh++) {
            int c = hh * 8 + gid;
            int jj = wn * 4 + (c >> 2);
            int gate = c & 3;
            int grow = gate * Hz + nb * 8 + jj;
            int k0 = s * 16 + t0 * 2;
            float w00 = wget(grow, k0,     W0, ld0, K0, W1, ld1, K1, W2, ld2);
            float w01 = wget(grow, k0 + 1, W0, ld0, K0, W1, ld1, K1, W2, ld2);
            float w10 = wget(grow, k0 + 8, W0, ld0, K0, W1, ld1, K1, W2, ld2);
            float w11 = wget(grow, k0 + 9, W0, ld0, K0, W1, ld1, K1, W2, ld2);
            r[hh * 2]     = bpack(w00, w01);
            r[hh * 2 + 1] = bpack(w10, w11);
        }
        Wp[idx] = make_uint4(r[0], r[1], r[2], r[3]);
    }
}

// ---------------- gates GEMM: one bulk-copy panel, 16-warp K-split ----------
template<bool DEC>
__device__ void gates_step(
    const uint4* __restrict__ Wp, float4* __restrict__ Ab,
    const __nv_bfloat16* __restrict__ psrc, int t,
    float* __restrict__ hout,
    __nv_bfloat16* __restrict__ pnext, int pstride,
    int mh, int nb, const float bias[2][4], const float* __restrict__ corr,
    float* __restrict__ scrR, uint32_t mbar)
{
    const int NCH  = DEC ? 36 : 20;
    const int KS16 = DEC ? 72 : 40;
    const int STR  = DEC ? DSTRF4 : ESTRF4;
    const int BYTES = 64 * STR * 16;
    int tid = threadIdx.x;
    int l = tid & 31, wrp = tid >> 5;
    bool hi = (wrp >= 8);
    int wm = wrp & 3, wn = (wrp >> 2) & 1;
    int gid = l >> 2, t0 = l & 3;
    int m16 = mh * 64 + wm * 16;
    int arow = wm * 16 + ((l >> 3) & 1) * 8 + (l & 7);
    int halfsel = l >> 4;
    uint32_t abase = s2u(Ab);

    if (tid == 0)
        asm volatile("mbarrier.init.shared.b64 [%0], %1;" :: "r"(mbar), "r"(1) : "memory");
    __syncthreads();
    if (tid == 0) {
        asm volatile("fence.proxy.async;" ::: "memory");
        asm volatile("mbarrier.arrive.expect_tx.shared.b64 _, [%0], %1;"
                     :: "r"(mbar), "r"(BYTES) : "memory");
        asm volatile("cp.async.bulk.shared::cta.global.mbarrier::complete_tx::bytes "
                     "[%0], [%1], %2, [%3];"
                     :: "r"(abase), "l"(psrc), "r"(BYTES), "r"(mbar) : "memory");
    }
    {   // all threads wait for panel (parity 0, fresh barrier each step)
        unsigned done = 0;
        while (!done) {
            asm volatile("{\n\t.reg .pred p;\n\t"
                "mbarrier.try_wait.parity.shared.b64 p, [%1], %2, 10000000;\n\t"
                "selp.b32 %0, 1, 0, p;\n\t}"
                : "=r"(done) : "r"(mbar), "r"(0u) : "memory");
        }
    }

    float acc[2][4];
    #pragma unroll
    for (int i = 0; i < 2; i++)
        #pragma unroll
        for (int k = 0; k < 4; k++) acc[i][k] = 0.f;

    uint32_t lbase = abase + (uint32_t)(arow * STR + halfsel) * 16;
    const uint4* wpp = Wp + (size_t)wn * KS16 * 32 + l;
    int c0 = hi ? (NCH / 2) : 0;
    #pragma unroll 2
    for (int cc = 0; cc < NCH / 2; cc++) {
        int ccg = c0 + cc;
        #pragma unroll
        for (int kk = 0; kk < 2; kk++) {
            uint32_t addr = lbase + (uint32_t)((ccg * 4 + kk * 2) * 16);
            uint32_t a0, a1, a2, a3;
            asm volatile("ldmatrix.sync.aligned.m8n8.x4.shared.b16 {%0,%1,%2,%3}, [%4];"
                         : "=r"(a0), "=r"(a1), "=r"(a2), "=r"(a3) : "r"(addr));
            uint4 wv = wpp[(size_t)(ccg * 2 + kk) * 32];
            mma16(acc[0], a0, a1, a2, a3, wv.x, wv.y);
            mma16(acc[1], a0, a1, a2, a3, wv.z, wv.w);
        }
    }
    if (hi) {
        float4* r4 = (float4*)scrR;
        r4[(wrp - 8) * 64 + l * 2]     = make_float4(acc[0][0], acc[0][1], acc[0][2], acc[0][3]);
        r4[(wrp - 8) * 64 + l * 2 + 1] = make_float4(acc[1][0], acc[1][1], acc[1][2], acc[1][3]);
    }
    __syncthreads();
    if (!hi) {
        float4 p0 = ((const float4*)scrR)[wrp * 64 + l * 2];
        float4 p1 = ((const float4*)scrR)[wrp * 64 + l * 2 + 1];
        acc[0][0] += p0.x; acc[0][1] += p0.y; acc[0][2] += p0.z; acc[0][3] += p0.w;
        acc[1][0] += p1.x; acc[1][1] += p1.y; acc[1][2] += p1.z; acc[1][3] += p1.w;

        bool evn = ((t0 & 1) == 0);
        #pragma unroll
        for (int hh = 0; hh < 2; hh++) {
            float d0 = acc[hh][0], d1 = acc[hh][1], d2 = acc[hh][2], d3 = acc[hh][3];
            float x0 = __shfl_xor_sync(0xffffffffu, d0, 1);
            float x1 = __shfl_xor_sync(0xffffffffu, d1, 1);
            float x2 = __shfl_xor_sync(0xffffffffu, d2, 1);
            float x3 = __shfl_xor_sync(0xffffffffu, d3, 1);
            int j = nb * 8 + wn * 4 + hh * 2 + (t0 >> 1);
            int b = m16 + gid + (evn ? 0 : 8);
            float gi = (evn ? d0 : x2) + bias[hh][0];
            float gf = (evn ? d1 : x3) + bias[hh][1];
            float gg = (evn ? x0 : d2) + bias[hh][2];
            float go = (evn ? x1 : d3) + bias[hh][3];
            if (corr) {
                gi -= corr[b * 2048 + j];
                gf -= corr[b * 2048 + 512 + j];
                gg -= corr[b * 2048 + 1024 + j];
                go -= corr[b * 2048 + 1536 + j];
            }
            float c  = g_c[b * Hz + j];
            float cn = sigm(gf) * c + sigm(gi) * tanhf(gg);
            float hn = sigm(go) * tanhf(cn);
            g_c[b * Hz + j] = cn;
            hout[b * Hz + j] = hn;
            pnext[(size_t)b * pstride + 128 + j] = __float2bfloat16(hn);
            if (!DEC)
                g_enc[((size_t)b * LCz + t) * Hz + j] = __float2bfloat16(hn);
        }
    }
}

__device__ __forceinline__ void load_bias2(float bias[2][4],
    const float* __restrict__ bih, const float* __restrict__ bhh,
    const float* __restrict__ beff, int nb)
{
    int l = threadIdx.x & 31;
    int wn = ((threadIdx.x >> 5) >> 2) & 1;
    int t0 = l & 3;
    #pragma unroll
    for (int hh = 0; hh < 2; hh++) {
        int j = nb * 8 + wn * 4 + hh * 2 + (t0 >> 1);
        #pragma unroll
        for (int g4 = 0; g4 < 4; g4++)
            bias[hh][g4] = beff ? beff[g4 * Hz + j] : (bih[g4 * Hz + j] + bhh[g4 * Hz + j]);
    }
}

// ---------------- pad compaction (512 threads) ------------------------------
__device__ void comp_scan(int b, const int* __restrict__ C_pad, float* smf)
{
    int* sm = (int*)smf;
    int tid = threadIdx.x, lane = tid & 31, w = tid >> 5;
    int f = (C_pad[b * LCz + tid] == 0) ? 1 : 0;
    int x = f;
    #pragma unroll
    for (int o = 1; o < 32; o <<= 1) {
        int y = __shfl_up_sync(0xffffffffu, x, o);
        if (lane >= o) x += y;
    }
    if (lane == 31) sm[w] = x;
    __syncthreads();
    if (tid == 0) {
        int run = 0;
        for (int i = 0; i < 16; i++) { int v = sm[i]; sm[16 + i] = run; run += v; }
        sm[32] = run;
    }
    __syncthreads();
    int excl = sm[16 + w] + x - f;
    if (f) g_lidx[b * LCz + excl] = tid;
    if (tid == 0) g_Lb[b] = sm[32];
    __syncthreads();
}

__device__ void build_F(int b, const float* __restrict__ att_W, float* se)
{
    int tid = threadIdx.x;
    int Lb = g_Lb[b];
    for (int ci0 = 0; ci0 < Lb; ci0 += 32) {
        int R = min(32, Lb - ci0);
        for (int idx = tid; idx < R * 512; idx += NTHR) {
            int r = idx >> 9, j = idx & 511;
            int l = g_lidx[b * LCz + ci0 + r];
            __nv_bfloat16 hv = g_enc[((size_t)b * LCz + l) * Hz + j];
            float fv = __bfloat162float(hv);
            se[j * 36 + r] = fv;
            g_encc[((size_t)b * LCz + ci0 + r) * Hz + j] = f2fp8(fv);
        }
        __syncthreads();
        {
            int k = tid;
            float acc[32];
            #pragma unroll
            for (int i = 0; i < 32; i++) acc[i] = 0.f;
            for (int j = 0; j < 512; j++) {
                float wv = att_W[j * Hz + k];
                #pragma unroll
                for (int g4 = 0; g4 < 8; g4++) {
                    float4 e = *(const float4*)&se[j * 36 + g4 * 4];
                    acc[g4 * 4 + 0] += e.x * wv;
                    acc[g4 * 4 + 1] += e.y * wv;
                    acc[g4 * 4 + 2] += e.z * wv;
                    acc[g4 * 4 + 3] += e.w * wv;
                }
            }
            for (int r = 0; r < R; r++)
                g_Fc[((size_t)b * LCz + ci0 + r) * Hz + k] = f2fp8(acc[r]);
        }
        __syncthreads();
    }
}

__device__ void calc_u(int b, const float* __restrict__ out_W,
                       const float* __restrict__ out_b, float* scr)
{
    int tid = threadIdx.x;
    __syncthreads();
    if (tid < Hz) scr[tid] = g_h[0][b * Hz + tid];
    __syncthreads();
    if (tid < Hz) {
        const float* wr = out_W + (size_t)tid * (2 * Hz);
        float acc = 0.f;
        for (int h = 0; h < Hz; h += 4) {
            float4 w4 = *(const float4*)(wr + h);
            acc += w4.x * scr[h] + w4.y * scr[h + 1] + w4.z * scr[h + 2] + w4.w * scr[h + 3];
        }
        g_u[b * Hz + tid] = acc + out_b[tid];
    }
    __syncthreads();
}

__device__ void compose(const float* __restrict__ dec_Wih, const float* __restrict__ dec_Whh,
                        const float* __restrict__ dec_bih, const float* __restrict__ dec_bhh,
                        const float* __restrict__ out_W, const float* __restrict__ out_b)
{
    int bid = blockIdx.x, tid = threadIdx.x;
    if (tid >= 256) return;
    int g = bid * 16 + (tid >> 4);
    int c0 = (tid & 15) * 32;
    const float* wv = dec_Wih + (size_t)g * (Vz + Hz) + Vz;
    #pragma unroll 1
    for (int pass = 0; pass < 2; pass++) {
        float acc[32];
        #pragma unroll
        for (int i = 0; i < 32; i++) acc[i] = 0.f;
        float accb = 0.f;
        for (int v = 0; v < Hz; v++) {
            float w = wv[v];
            const float* owr = out_W + (size_t)v * (2 * Hz) + pass * Hz + c0;
            #pragma unroll
            for (int i = 0; i < 32; i += 4) {
                float4 o = *(const float4*)(owr + i);
                acc[i] += w * o.x; acc[i + 1] += w * o.y;
                acc[i + 2] += w * o.z; acc[i + 3] += w * o.w;
            }
            if (pass == 0) accb += w * out_b[v];
        }
        if (pass == 0) {
            for (int i = 0; i < 32; i++)
                g_Weff[(size_t)g * Hz + c0 + i] = dec_Whh[(size_t)g * Hz + c0 + i] + acc[i];
            if ((tid & 15) == 0) g_beff[g] = dec_bih[g] + dec_bhh[g] + accb;
        } else {
            for (int i = 0; i < 32; i++)
                g_Wcomp[(size_t)g * Hz + c0 + i] = acc[i];
        }
    }
}

__device__ void calc_c(int b, const float* __restrict__ dec_Wih, float* scr)
{
    int tid = threadIdx.x;
    __syncthreads();
    if (tid < Hz) scr[tid] = g_u[b * Hz + tid];
    __syncthreads();
    for (int g = tid; g < 2048; g += NTHR) {
        const float* wv = dec_Wih + (size_t)g * (Vz + Hz) + Vz;
        float acc = 0.f;
        for (int v = 0; v < Hz; v += 4) {
            float4 w4 = *(const float4*)(wv + v);
            acc += w4.x * scr[v] + w4.y * scr[v + 1] + w4.z * scr[v + 2] + w4.w * scr[v + 3];
        }
        g_corr[b * 2048 + g] = acc;
    }
}

// ---------------- attention (group A: 256 threads, fp8 streams) --------------
__device__ void attn_block(int b, const float* __restrict__ hcur,
                           float* __restrict__ dst, __nv_bfloat16* __restrict__ dstb_row,
                           float* sm)
{
    float* ss   = sm;
    float* red  = sm + 512;
    float* sca  = sm + 520;
    float* wacc = sm + 528;
    int tid = threadIdx.x, lane = tid & 31, w = tid >> 5;
    int Lb = g_Lb[b];

    float qreg[16];
    const float* hb = hcur + b * Hz + lane * 16;
    #pragma unroll
    for (int i = 0; i < 16; i += 4) {
        float4 v = *(const float4*)(hb + i);
        qreg[i] = v.x; qreg[i + 1] = v.y; qreg[i + 2] = v.z; qreg[i + 3] = v.w;
    }

    const unsigned char* Fb = g_Fc + (size_t)b * LCz * Hz;
    #pragma unroll 4
    for (int l = w; l < Lb; l += 8) {
        uint4 u0 = *(const uint4*)(Fb + (size_t)l * Hz + lane * 16);
        const unsigned short* p2 = (const unsigned short*)&u0;
        float acc = 0.f;
        #pragma unroll
        for (int i = 0; i < 8; i++) {
            float2 f = fp8x2_to_f2(p2[i]);
            acc += f.x * qreg[2 * i] + f.y * qreg[2 * i + 1];
        }
        #pragma unroll
        for (int o = 16; o > 0; o >>= 1) acc += __shfl_xor_sync(0xffffffffu, acc, o);
        if (lane == 0) ss[l] = acc;
    }
    NB(1);

    float m = -INFINITY;
    for (int l = tid; l < Lb; l += 256) m = fmaxf(m, ss[l]);
    #pragma unroll
    for (int o = 16; o > 0; o >>= 1) m = fmaxf(m, __shfl_xor_sync(0xffffffffu, m, o));
    if (lane == 0) red[w] = m;
    NB(1);
    if (tid == 0) {
        float mm = red[0];
        for (int i = 1; i < 8; i++) mm = fmaxf(mm, red[i]);
        sca[0] = mm;
    }
    NB(1);
    float bmax = sca[0];

    float s = 0.f;
    for (int l = tid; l < Lb; l += 256) {
        float e = expf(ss[l] - bmax);
        ss[l] = e;
        s += e;
    }
    #pragma unroll
    for (int o = 16; o > 0; o >>= 1) s += __shfl_xor_sync(0xffffffffu, s, o);
    if (lane == 0) red[w] = s;
    NB(1);
    if (tid == 0) {
        float t2 = 0.f;
        for (int i = 0; i < 8; i++) t2 += red[i];
        sca[1] = t2;
    }
    NB(1);
    float inv = 1.f / sca[1];

    float acc2[16];
    #pragma unroll
    for (int i = 0; i < 16; i++) acc2[i] = 0.f;
    const unsigned char* Eb = g_encc + (size_t)b * LCz * Hz;
    #pragma unroll 4
    for (int l = w; l < Lb; l += 8) {
        float d = ss[l];
        uint4 u0 = *(const uint4*)(Eb + (size_t)l * Hz + lane * 16);
        const unsigned short* p2 = (const unsigned short*)&u0;
        #pragma unroll
        for (int i = 0; i < 8; i++) {
            float2 f = fp8x2_to_f2(p2[i]);
            acc2[2 * i]     += d * f.x;
            acc2[2 * i + 1] += d * f.y;
        }
    }
    #pragma unroll
    for (int i = 0; i < 16; i++) wacc[w * Hz + lane * 16 + i] = acc2[i];
    NB(1);

    for (int h = tid; h < Hz; h += 256) {
        float t2 = 0.f;
        #pragma unroll
        for (int ww = 0; ww < 8; ww++) t2 += wacc[ww * Hz + h];
        float v = t2 * inv;
        dst[b * Hz + h] = v;
        dstb_row[h] = __float2bfloat16(v);
    }
}

// ---------------- out-proj (group B, double-buffered scrB) -------------------
__device__ void outproj16(const float* __restrict__ h_src,
                          const float* __restrict__ attn_src,
                          const float* __restrict__ out_b,
                          float* __restrict__ vout, float* sm, int mh, int t256)
{
    NB(2);
    int bid = blockIdx.x;
    int gb = bid >> 1;
    int m0 = mh * 64 + (gb & 3) * 16;
    int n0 = ((gb >> 2) & 7) * 64;
    int split = (gb >> 5) & 1;
    const float* Asrc = (split == 0) ? h_src : attn_src;

    int arow = t256 & 15, akg = t256 >> 4;
    int wr = t256 >> 2, wkg = t256 & 3;
    int m = t256 >> 4, ng = t256 & 15;

    const float* ap = Asrc + (size_t)(m0 + arow) * Hz + akg * 8;
    const __nv_bfloat16* wp = g_oWb16 + (size_t)(n0 + wr) * 1024 + split * Hz + wkg * 8;

    float4 pa0, pa1;
    uint4 pw;
    if (t256 < 64) { pa0 = *(const float4*)ap; pa1 = *(const float4*)(ap + 4); }
    pw = *(const uint4*)wp;

    float acc[4] = {0.f, 0.f, 0.f, 0.f};
    for (int it = 0; it < 16; it++) {
        float* As = sm + (it & 1) * 2560;
        float* Ws = As + 512;
        if (t256 < 64) {
            int kb = akg * 8;
            As[(kb + 0) * 16 + arow] = pa0.x; As[(kb + 1) * 16 + arow] = pa0.y;
            As[(kb + 2) * 16 + arow] = pa0.z; As[(kb + 3) * 16 + arow] = pa0.w;
            As[(kb + 4) * 16 + arow] = pa1.x; As[(kb + 5) * 16 + arow] = pa1.y;
            As[(kb + 6) * 16 + arow] = pa1.z; As[(kb + 7) * 16 + arow] = pa1.w;
        }
        {
            int kb = wkg * 8;
            const __nv_bfloat162* ph = (const __nv_bfloat162*)&pw;
            #pragma unroll
            for (int i = 0; i < 4; i++) {
                float2 f = __bfloat1622float2(ph[i]);
                Ws[(kb + 2 * i) * 64 + wr]     = f.x;
                Ws[(kb + 2 * i + 1) * 64 + wr] = f.y;
            }
        }
        NB(2);
        if (it < 15) {
            if (t256 < 64) {
                const float* ap2 = ap + (it + 1) * 32;
                pa0 = *(const float4*)ap2; pa1 = *(const float4*)(ap2 + 4);
            }
            pw = *(const uint4*)(wp + (it + 1) * 32);
        }
        #pragma unroll
        for (int kk = 0; kk < 32; kk++) {
            float a = As[kk * 16 + m];
            float4 w4 = *(const float4*)&Ws[kk * 64 + ng * 4];
            acc[0] += a * w4.x; acc[1] += a * w4.y;
            acc[2] += a * w4.z; acc[3] += a * w4.w;
        }
    }
    NB(2);
    #pragma unroll
    for (int i = 0; i < 4; i++) {
        int n = n0 + ng * 4 + i;
        float v = acc[i] + ((split == 0) ? out_b[n] : 0.f);
        vout[(size_t)split * BHS + (m0 + m) * Hz + n] = v;
    }
}

// ---------------- logits + CE (256 threads, given barrier id) ----------------
__device__ void logits_ce(int b, int tt, const int* __restrict__ E,
                          const float* __restrict__ vp,
                          const float* __restrict__ voc_b, float* sm,
                          int t256, int barid)
{
    float* st = sm;
    float* sl = sm + 512;
    int lane = t256 & 31, w = t256 >> 5;
    NB(barid);

    for (int i = t256; i < Hz; i += 256)
        st[i] = tanhf(vp[b * Hz + i] + vp[BHS + b * Hz + i]);
    NB(barid);

    float sreg[16];
    #pragma unroll
    for (int i = 0; i < 16; i++) sreg[i] = st[lane * 16 + i];

    for (int v = w; v < Vz; v += 8) {
        const __nv_bfloat16* wr = g_vocb16 + (size_t)v * Hz + lane * 16;
        uint4 u0 = *(const uint4*)wr;
        uint4 u1 = *(const uint4*)(wr + 8);
        const __nv_bfloat162* h0 = (const __nv_bfloat162*)&u0;
        const __nv_bfloat162* h1 = (const __nv_bfloat162*)&u1;
        float acc = 0.f;
        #pragma unroll
        for (int i = 0; i < 4; i++) {
            float2 f0 = __bfloat1622float2(h0[i]);
            float2 f1 = __bfloat1622float2(h1[i]);
            acc += f0.x * sreg[2 * i]     + f0.y * sreg[2 * i + 1];
            acc += f1.x * sreg[8 + 2 * i] + f1.y * sreg[8 + 2 * i + 1];
        }
        #pragma unroll
        for (int o = 16; o > 0; o >>= 1) acc += __shfl_xor_sync(0xffffffffu, acc, o);
        if (lane == 0) sl[v] = acc + voc_b[v];
    }
    NB(barid);

    if (w == 0) {
        float m = -INFINITY;
        for (int v = lane; v < Vz; v += 32) m = fmaxf(m, sl[v]);
        #pragma unroll
        for (int o = 16; o > 0; o >>= 1) m = fmaxf(m, __shfl_xor_sync(0xffffffffu, m, o));
        float s = 0.f;
        for (int v = lane; v < Vz; v += 32) s += expf(sl[v] - m);
        #pragma unroll
        for (int o = 16; o > 0; o >>= 1) s += __shfl_xor_sync(0xffffffffu, s, o);
        if (lane == 0) {
            int tv = E[b * LEz + tt + 1];
            int idx = b * TDEC + tt;
            if (tv != 0) { g_nll[idx] = m + logf(s) - sl[tv]; g_msk[idx] = 1.f; }
            else         { g_nll[idx] = 0.f;                  g_msk[idx] = 0.f; }
        }
    }
    NB(barid);
}

// ---------------- the single persistent kernel ------------------------------
__global__ void __launch_bounds__(NTHR, 1) persist_kernel(
    const float* __restrict__ C,       const int* __restrict__ C_pad,
    const int* __restrict__ E,         const float* __restrict__ E_emb,
    const float* __restrict__ enc_Wih, const float* __restrict__ enc_Whh,
    const float* __restrict__ enc_bih, const float* __restrict__ enc_bhh,
    const float* __restrict__ dec_Wih, const float* __restrict__ dec_Whh,
    const float* __restrict__ dec_bih, const float* __restrict__ dec_bhh,
    const float* __restrict__ att_W,   const float* __restrict__ out_W,
    const float* __restrict__ out_b,   const float* __restrict__ voc_W,
    const float* __restrict__ voc_b,   float* __restrict__ out)
{
    extern __shared__ __align__(16) float4 dsm[];
    uint4*  Wp   = (uint4*)dsm;
    float4* Ab   = dsm + 4608;
    float*  scrA = (float*)(dsm + 4608);       // aliases Ab (phase-B / pre-dec)
    float*  scrB = scrA + 4624;
    float*  scrR = (float*)(dsm + 13889);      // K-split reduce (8KB)
    uint32_t mbar = s2u((char*)dsm + 13888 * 16);

    int bid = blockIdx.x, tid = threadIdx.x;
    int lane = tid & 31, w = tid >> 5;
    int mh = bid & 1, nb = bid >> 1;
    int mhb = mh * 64 + nb;

    // ---- init: state, bf16 packs, panel x-columns ----
    for (int i = bid * NTHR + tid; i < BHS; i += NBLK * NTHR) { g_h[0][i] = 0.f; g_c[i] = 0.f; }
    float* vpf = (float*)g_vp;
    for (int i = bid * NTHR + tid; i < 4 * BHS; i += NBLK * NTHR) vpf[i] = 0.f;
    float* apf = (float*)g_attn2;
    for (int i = bid * NTHR + tid; i < 2 * BHS; i += NBLK * NTHR) apf[i] = 0.f;
    for (int i = bid * NTHR + tid; i < Vz * Hz; i += NBLK * NTHR)
        g_vocb16[i] = __float2bfloat16(voc_W[i]);
    for (int i = bid * NTHR + tid; i < 512 * 1024; i += NBLK * NTHR)
        g_oWb16[i] = __float2bfloat16(out_W[i]);
    // x columns of both panel sets (E_emb -> dec, C -> enc)
    for (size_t i = bid * NTHR + tid; i < (size_t)512 * 128 * 128; i += (size_t)NBLK * NTHR) {
        int col = (int)(i & 127);
        size_t r = i >> 7;            // t*128 + b
        int b = (int)(r & 127);
        int t = (int)(r >> 7);
        g_ApD[r * DSTR + col] = __float2bfloat16(E_emb[((size_t)b * LEz + t) * Vz + col]);
        g_ApE[r * ESTR + col] = __float2bfloat16(C[((size_t)b * LCz + t) * Vz + col]);
    }
    // enc panel 0 h-columns = 0
    for (int i = bid * NTHR + tid; i < 128 * 512; i += NBLK * NTHR) {
        int b = i >> 9, h = i & 511;
        g_ApE[(size_t)b * ESTR + 128 + h] = __float2bfloat16(0.f);
    }
    gsync_all();

    // ---- encoder ----
    pack_Wb3(Wp, nb, 40, enc_Wih, Vz, Vz, enc_Whh, Hz, Hz, enc_Whh, Hz);
    __syncthreads();
    float biasE[2][4];
    load_bias2(biasE, enc_bih, enc_bhh, nullptr, nb);
    for (int t = 0; t < LCz; t++) {
        const __nv_bfloat16* psrc = g_ApE + ((size_t)t * 128 + mh * 64) * ESTR;
        __nv_bfloat16* pnext = (t < 511) ? (g_ApE + (size_t)(t + 1) * 128 * ESTR) : g_ApD;
        int pstride = (t < 511) ? ESTR : DSTR;    // enc t=511 writes hT into dec panel 0
        gates_step<false>(Wp, Ab, psrc, t, g_h[1 - (t & 1)],
                          pnext, pstride, mh, nb, biasE, nullptr, scrR, mbar);
        asm volatile("fence.proxy.async;" ::: "memory");
        gsync_g(mh, nb);
    }

    // ---- pre-decoder (own batch) ----
    comp_scan(mhb, C_pad, scrA);
    build_F(mhb, att_W, (float*)dsm);
    calc_u(mhb, out_W, out_b, scrA);
    calc_c(mhb, dec_Wih, scrA);
    // dec panel 0: attn(-1) = 0 (own batch row)
    for (int i = tid; i < 512; i += NTHR)
        g_ApD[(size_t)mhb * DSTR + 640 + i] = __float2bfloat16(0.f);

    // ---- composition (shared) => full barrier ----
    compose(dec_Wih, dec_Whh, dec_bih, dec_bhh, out_W, out_b);
    gsync_all();

    // ---- decoder ----
    pack_Wb3(Wp, nb, 72, dec_Wih, Vz + Hz, Vz, g_Weff, Hz, Hz, g_Wcomp, Hz);
    __syncthreads();
    float biasD[2][4];
    load_bias2(biasD, dec_bih, dec_bhh, g_beff, nb);

    for (int t = 0; t < TDEC; t++) {
        // Phase A: gates(t) — bulk panel + 16-warp K-split mma
        const __nv_bfloat16* psrc = g_ApD + ((size_t)t * 128 + mh * 64) * DSTR;
        __nv_bfloat16* pnext = g_ApD + (size_t)(t + 1) * 128 * DSTR;
        gates_step<true>(Wp, Ab, psrc, t, g_h[1 - (t & 1)],
                         pnext, DSTR, mh, nb, biasD,
                         (t == 0) ? g_corr : nullptr, scrR, mbar);
        asm volatile("fence.proxy.async;" ::: "memory");
        gsync_g(mh, nb);

        // Phase B: group A attn(t) || group B outproj(t-1) + CE(t-2)
        if (tid < 256) {
            __nv_bfloat16* arow = g_ApD + ((size_t)(t + 1) * 128 + mhb) * DSTR + 640;
            attn_block(mhb, g_h[1 - (t & 1)], g_attn2[t & 1], arow, scrA);
        } else {
            int t256 = tid - 256;
            if (t >= 1)
                outproj16(g_h[t & 1], g_attn2[(t + 1) & 1], out_b,
                          (float*)g_vp[(t + 1) & 1], scrB, mh, t256);
            if (t >= 2)
                logits_ce(mhb, t - 2, E, (const float*)g_vp[t & 1], voc_b, scrB,
                          t256, 2);
        }
        asm volatile("fence.proxy.async;" ::: "memory");
        gsync_g(mh, nb);
    }

    // ---- tail: outproj(510) (group B) || CE(509) (group A); then CE(510) ----
    if (tid < 256) {
        logits_ce(mhb, TDEC - 2, E, (const float*)g_vp[1], voc_b, scrA, tid, 1);
    } else {
        outproj16(g_h[1], g_attn2[0], out_b, (float*)g_vp[0], scrB, mh, tid - 256);
    }
    gsync_g(mh, nb);
    if (tid < 256)
        logits_ce(mhb, TDEC - 1, E, (const float*)g_vp[0], voc_b, scrA, tid, 1);
    __syncthreads();

    // ---- per-batch reduction ----
    {
        float s = 0.f, c = 0.f;
        for (int i = tid; i < TDEC; i += NTHR) {
            s += g_nll[mhb * TDEC + i];
            c += g_msk[mhb * TDEC + i];
        }
        #pragma unroll
        for (int o = 16; o > 0; o >>= 1) {
            s += __shfl_xor_sync(0xffffffffu, s, o);
            c += __shfl_xor_sync(0xffffffffu, c, o);
        }
        __syncthreads();
        if (lane == 0) { scrA[w] = s; scrA[16 + w] = c; }
        __syncthreads();
        if (tid == 0) {
            float ts = 0.f, tc = 0.f;
            for (int i = 0; i < 16; i++) { ts += scrA[i]; tc += scrA[16 + i]; }
            g_ps[bid] = ts; g_pc[bid] = tc;
        }
    }
    gsync_all();
    if (bid == 0 && tid == 0) {
        float ts = 0.f, tc = 0.f;
        for (int i = 0; i < NBLK; i++) { ts += g_ps[i]; tc += g_pc[i]; }
        out[0] = ts / fmaxf(tc, 1.f);
    }
}

// ---------------- host entry ------------------------------------------------
extern "C" void kernel_launch(void* const* d_in, const int* in_sizes, int n_in,
                              void* d_out, int out_size)
{
    cudaFuncSetAttribute((const void*)persist_kernel,
                         cudaFuncAttributeMaxDynamicSharedMemorySize, SMEM_BYTES);
    persist_kernel<<<NBLK, NTHR, SMEM_BYTES>>>(
        (const float*)d_in[0],  (const int*)d_in[1],
        (const int*)d_in[2],    (const float*)d_in[3],
        (const float*)d_in[4],  (const float*)d_in[5],
        (const float*)d_in[6],  (const float*)d_in[7],
        (const float*)d_in[8],  (const float*)d_in[9],
        (const float*)d_in[10], (const float*)d_in[11],
        (const float*)d_in[12], (const float*)d_in[13],
        (const float*)d_in[14], (const float*)d_in[15],
        (const float*)d_in[16], (float*)d_out);
}